// round 2
// baseline (speedup 1.0000x reference)
#include <cuda_runtime.h>
#include <cstdint>
#include <cstddef>

#define BB 64
#define TT 1024
#define II 512
#define HH 512
#define GC4 2048   // 4*H

// ---------------- device scratch (no allocations allowed) ----------------
__device__ float g_xp[(size_t)TT * GC4 * BB];   // [t][gc][b]  512 MB
__device__ float g_Wcat[(size_t)II * GC4];      // [k][gc]
__device__ float g_bsum[GC4];
__device__ float g_h[2][BB * HH];               // double-buffered h
__device__ unsigned g_barCnt[4];

// ---------------- pack weights / bias, zero h0, reset barriers ----------------
__global__ __launch_bounds__(256) void pack_kernel(
    const float* __restrict__ Wif, const float* __restrict__ Wii,
    const float* __restrict__ Wig, const float* __restrict__ Wio,
    const float* __restrict__ bif, const float* __restrict__ bhf,
    const float* __restrict__ bii, const float* __restrict__ bhi,
    const float* __restrict__ big_, const float* __restrict__ bhg,
    const float* __restrict__ bio, const float* __restrict__ bho)
{
    int idx = blockIdx.x * 256 + threadIdx.x;
    if (idx < II * GC4) {
        int k = idx / GC4, gc = idx % GC4;
        int gate = gc >> 9, j = gc & 511;
        const float* W = (gate == 0) ? Wif : (gate == 1) ? Wii : (gate == 2) ? Wig : Wio;
        g_Wcat[idx] = W[k * HH + j];
    }
    if (idx < GC4) {
        int gate = idx >> 9, j = idx & 511;
        const float* bx = (gate == 0) ? bif : (gate == 1) ? bii : (gate == 2) ? big_ : bio;
        const float* bh = (gate == 0) ? bhf : (gate == 1) ? bhi : (gate == 2) ? bhg : bho;
        g_bsum[idx] = bx[j] + bh[j];
    }
    if (idx < BB * HH) g_h[0][idx] = 0.f;
    if (idx < 4) g_barCnt[idx] = 0u;
}

// ---------------- phase 1: xp[t][gc][b] = sum_k Wcat[k][gc] * x[b][t][k] + bsum[gc] ----------------
// n = t*64 + b ; block tile 128(gc) x 128(n) ; 256 threads ; 8x8 per thread
__global__ __launch_bounds__(256) void xproj_kernel(const float* __restrict__ x)
{
    __shared__ float A_s[16 * 128];   // Wcat tile [kk][gc]
    __shared__ float B_s[16 * 132];   // x tile    [kk][n]
    int tid = threadIdx.x;
    int tx = tid & 15, ty = tid >> 4;
    int gc0 = blockIdx.x * 128;
    int n0  = blockIdx.y * 128;

    float acc[8][8];
#pragma unroll
    for (int r = 0; r < 8; r++)
#pragma unroll
        for (int c = 0; c < 8; c++) acc[r][c] = 0.f;

    for (int k0 = 0; k0 < II; k0 += 16) {
#pragma unroll
        for (int v = 0; v < 2; v++) {
            int u = tid + v * 256;
            int kk = u >> 5, g4 = u & 31;
            *(float4*)&A_s[kk * 128 + g4 * 4] =
                *(const float4*)&g_Wcat[(size_t)(k0 + kk) * GC4 + gc0 + g4 * 4];
        }
#pragma unroll
        for (int v = 0; v < 2; v++) {
            int u = tid + v * 256;
            int nl = u & 127, kq = u >> 7;
            int n = n0 + nl, b = n & 63, t = n >> 6;
            float4 xv = *(const float4*)&x[((size_t)b * TT + t) * II + k0 + kq * 4];
            B_s[(kq * 4 + 0) * 132 + nl] = xv.x;
            B_s[(kq * 4 + 1) * 132 + nl] = xv.y;
            B_s[(kq * 4 + 2) * 132 + nl] = xv.z;
            B_s[(kq * 4 + 3) * 132 + nl] = xv.w;
        }
        __syncthreads();
#pragma unroll
        for (int kk = 0; kk < 16; kk++) {
            float4 a0 = *(float4*)&A_s[kk * 128 + ty * 4];
            float4 a1 = *(float4*)&A_s[kk * 128 + 64 + ty * 4];
            float4 b0 = *(float4*)&B_s[kk * 132 + tx * 4];
            float4 b1 = *(float4*)&B_s[kk * 132 + 64 + tx * 4];
            float ar[8] = {a0.x, a0.y, a0.z, a0.w, a1.x, a1.y, a1.z, a1.w};
            float bc[8] = {b0.x, b0.y, b0.z, b0.w, b1.x, b1.y, b1.z, b1.w};
#pragma unroll
            for (int r = 0; r < 8; r++)
#pragma unroll
                for (int c = 0; c < 8; c++)
                    acc[r][c] = fmaf(ar[r], bc[c], acc[r][c]);
        }
        __syncthreads();
    }

    int t0 = n0 >> 6;   // block covers exactly 2 timesteps, all 64 batches
#pragma unroll
    for (int r = 0; r < 8; r++) {
        int gc = gc0 + ((r < 4) ? (ty * 4 + r) : (64 + ty * 4 + r - 4));
        float bias = g_bsum[gc];
        float4 v0 = make_float4(acc[r][0] + bias, acc[r][1] + bias,
                                acc[r][2] + bias, acc[r][3] + bias);
        float4 v1 = make_float4(acc[r][4] + bias, acc[r][5] + bias,
                                acc[r][6] + bias, acc[r][7] + bias);
        *(float4*)&g_xp[((size_t)t0 * GC4 + gc) * BB + tx * 4] = v0;
        *(float4*)&g_xp[((size_t)(t0 + 1) * GC4 + gc) * BB + tx * 4] = v1;
    }
}

// ---------------- phase 2: persistent recurrent kernel ----------------
// 128 blocks = 4 batch-groups (16 b) x 32 col-groups (16 hcols x 4 gates)
// tid = ks*64 + jj*4 + bq : warp = 8 jj x 4 bq, fixed ks (k-split 4)
// SMEM (floats): W_s 32768 | h_s 8192 | part 3*1088
#define SMEM_FLOATS (32768 + 8192 + 3 * 1088)

__global__ __launch_bounds__(256, 1) void lstm_kernel(
    float* __restrict__ out,
    const float* __restrict__ Whf, const float* __restrict__ Whi,
    const float* __restrict__ Whg, const float* __restrict__ Who)
{
    extern __shared__ float smem[];
    float4* W_s4 = (float4*)smem;             // [k*16 + jj] -> gates f,i,g,o
    float4* h_s4 = (float4*)(smem + 32768);   // [b*128 + (k4 ^ (b&7))]
    float*  part = smem + 32768 + 8192;       // [(ks-1)*1088 + og*17 + r]

    const int tid = threadIdx.x;
    const int bq = tid & 3;
    const int jj = (tid >> 2) & 15;
    const int ks = tid >> 6;
    const int bg = blockIdx.x >> 5;
    const int cg = blockIdx.x & 31;
    const int hcol = cg * 16 + jj;

    // preload Wh slice once (resident for all 1024 steps)
    for (int u = tid; u < 8192; u += 256) {
        int k = u >> 4, jl = u & 15;
        int hc = cg * 16 + jl;
        float4 w;
        w.x = Whf[k * HH + hc];
        w.y = Whi[k * HH + hc];
        w.z = Whg[k * HH + hc];
        w.w = Who[k * HH + hc];
        W_s4[k * 16 + jl] = w;
    }

    int bbase[4], sw[4];
#pragma unroll
    for (int i = 0; i < 4; i++) {
        int b = bq * 4 + i;
        bbase[i] = b * 128;
        sw[i] = b & 7;
    }
    float cst[4] = {0.f, 0.f, 0.f, 0.f};
    float acc[16];
    const int kb0 = ks * 32;   // k4-granule base for this k-split

    for (int t = 0; t < TT; t++) {
        const int cur = t & 1;
        // ingest h(t) from global (L2) into swizzled smem
        for (int u = tid; u < 2048; u += 256) {
            int b = u >> 7, k4 = u & 127;
            float4 v = __ldcv((const float4*)&g_h[cur][(bg * 16 + b) * HH + k4 * 4]);
            h_s4[b * 128 + (k4 ^ (b & 7))] = v;
        }
        __syncthreads();

#pragma unroll
        for (int r = 0; r < 16; r++) acc[r] = 0.f;

#pragma unroll 4
        for (int q = 0; q < 32; q++) {
            int k4g = kb0 + q;
            float wk[4][4];   // [kk][gate]
#pragma unroll
            for (int kk = 0; kk < 4; kk++) {
                float4 w = W_s4[(k4g * 4 + kk) * 16 + jj];
                wk[kk][0] = w.x; wk[kk][1] = w.y; wk[kk][2] = w.z; wk[kk][3] = w.w;
            }
#pragma unroll
            for (int i = 0; i < 4; i++) {
                float4 hq = h_s4[bbase[i] + (k4g ^ sw[i])];
                float hk[4] = {hq.x, hq.y, hq.z, hq.w};
#pragma unroll
                for (int kk = 0; kk < 4; kk++)
#pragma unroll
                    for (int g = 0; g < 4; g++)
                        acc[i * 4 + g] = fmaf(hk[kk], wk[kk][g], acc[i * 4 + g]);
            }
        }

        // cross-ks reduction through smem
        if (ks != 0) {
            float* p = &part[(ks - 1) * 1088 + (tid & 63) * 17];
#pragma unroll
            for (int r = 0; r < 16; r++) p[r] = acc[r];
        }
        __syncthreads();

        if (ks == 0) {
#pragma unroll
            for (int s = 0; s < 3; s++) {
                float* p = &part[s * 1088 + tid * 17];
#pragma unroll
                for (int r = 0; r < 16; r++) acc[r] += p[r];
            }
            // add xp and apply gates
            int bcol = bg * 16 + bq * 4;
            float xa[4][4];   // [gate][i]
#pragma unroll
            for (int g = 0; g < 4; g++) {
                float4 v = *(const float4*)&g_xp[((size_t)t * GC4 + g * 512 + hcol) * BB + bcol];
                xa[g][0] = v.x; xa[g][1] = v.y; xa[g][2] = v.z; xa[g][3] = v.w;
            }
#pragma unroll
            for (int i = 0; i < 4; i++) {
                float vf = acc[i * 4 + 0] + xa[0][i];
                float vi = acc[i * 4 + 1] + xa[1][i];
                float vg = acc[i * 4 + 2] + xa[2][i];
                float vo = acc[i * 4 + 3] + xa[3][i];
                float f  = 1.f / (1.f + __expf(-vf));
                float ii = 1.f / (1.f + __expf(-vi));
                float gg = tanhf(vg);
                float o  = 1.f / (1.f + __expf(-vo));
                cst[i] = f * cst[i] + ii * gg;
                float h = o * tanhf(cst[i]);
                int b = bg * 16 + bq * 4 + i;
                g_h[1 - cur][b * HH + hcol] = h;
                if (t == TT - 1) {
                    out[b * HH + hcol] = h;
                    out[BB * HH + b * HH + hcol] = cst[i];
                }
            }
        }

        // release h(t+1), barrier across this batch-group's 32 blocks
        __threadfence();
        __syncthreads();
        if (tid == 0) {
            atomicAdd(&g_barCnt[bg], 1u);
            unsigned tgt = 32u * (unsigned)(t + 1);
            while (*((volatile unsigned*)&g_barCnt[bg]) < tgt) { }
            __threadfence();
        }
        __syncthreads();
    }
}

extern "C" void kernel_launch(void* const* d_in, const int* in_sizes, int n_in,
                              void* d_out, int out_size)
{
    (void)in_sizes; (void)n_in; (void)out_size;
    const float* x    = (const float*)d_in[0];
    const float* W_ii = (const float*)d_in[1];
    const float* W_hi = (const float*)d_in[2];
    const float* W_if = (const float*)d_in[3];
    const float* W_hf = (const float*)d_in[4];
    const float* W_ig = (const float*)d_in[5];
    const float* W_hg = (const float*)d_in[6];
    const float* W_io = (const float*)d_in[7];
    const float* W_ho = (const float*)d_in[8];
    const float* b_ii = (const float*)d_in[9];
    const float* b_hi = (const float*)d_in[10];
    const float* b_if = (const float*)d_in[11];
    const float* b_hf = (const float*)d_in[12];
    const float* b_ig = (const float*)d_in[13];
    const float* b_hg = (const float*)d_in[14];
    const float* b_io = (const float*)d_in[15];
    const float* b_ho = (const float*)d_in[16];
    float* out = (float*)d_out;

    pack_kernel<<<4096, 256>>>(W_if, W_ii, W_ig, W_io,
                               b_if, b_hf, b_ii, b_hi,
                               b_ig, b_hg, b_io, b_ho);

    xproj_kernel<<<dim3(16, 512), 256>>>(x);

    int smem_bytes = SMEM_FLOATS * (int)sizeof(float);   // 176,896 B
    cudaFuncSetAttribute(lstm_kernel,
                         cudaFuncAttributeMaxDynamicSharedMemorySize, smem_bytes);
    lstm_kernel<<<128, 256, smem_bytes>>>(out, W_hf, W_hi, W_hg, W_ho);
}